// round 5
// baseline (speedup 1.0000x reference)
#include <cuda_runtime.h>
#include <cstdint>

#define NQ 14
#define NL 6
#define DIM 16384
#define NG (NL * NQ)                 // 84 rotation gates
#define NTHREADS 512
#define AMPS_PER_THREAD (DIM / NTHREADS)      // 32
#define NWARPS (NTHREADS / 32)
#define NGROUPS (NL * 3)             // 3 fused groups per layer (5,5,4)

typedef unsigned long long u64;

// ---- packed f32x2 helpers (sm_103a: ptxas never emits FFMA2 from C++) ----
#define PK2(r, a, b)   asm("mov.b64 %0, {%1,%2};" : "=l"(r) : "f"(a), "f"(b))
#define UPK2(a, b, r)  asm("mov.b64 {%0,%1}, %2;" : "=f"(a), "=f"(b) : "l"(r))
#define FMA2(d, a, b, c) asm("fma.rn.f32x2 %0, %1, %2, %3;" : "=l"(d) : "l"(a), "l"(b), "l"(c))
#define MUL2(d, a, b)    asm("mul.rn.f32x2 %0, %1, %2;" : "=l"(d) : "l"(a), "l"(b))

// One fused gate-group: K gates (5 or 4) with commuting targets.
struct Group {
    unsigned short loc2glob[32];  // local coset index -> XOR offset (XOR of masks)
    unsigned short row[5];        // parity rows (true-qubit bit of an index)
    unsigned char  npos[10];      // non-pivot bit positions (coset-rep expansion)
    unsigned char  gbase;         // first gate index into g_gates
};
struct Tab2 {
    Group grp[NGROUPS];
    unsigned short mrow0, mrow1;  // measurement parity rows
};

__device__ float2 g_gates[NG][4];   // [g][u00,u01,u10,u11]

__global__ void prep_gates_kernel(const float* __restrict__ w) {
    int g = blockIdx.x * blockDim.x + threadIdx.x;
    if (g >= NG) return;
    float phi   = w[g * 3 + 0];
    float theta = w[g * 3 + 1];
    float omega = w[g * 3 + 2];
    float st, ct;
    sincosf(theta * 0.5f, &st, &ct);
    float ssp, csp, ssm, csm;
    sincosf(0.5f * (phi + omega), &ssp, &csp);
    sincosf(0.5f * (phi - omega), &ssm, &csm);
    g_gates[g][0] = make_float2( csp * ct, -ssp * ct);
    g_gates[g][1] = make_float2(-csm * st, -ssm * st);
    g_gates[g][2] = make_float2( csm * st, -ssm * st);
    g_gates[g][3] = make_float2( csp * ct,  ssp * ct);
}

// Apply one fused group. Statevector is SoA: sx[i], sy[i].
// Packing: local bit 0 (= gate 0's pair bit) lives inside the f32x2 lanes.
// Gate 0 is applied SCALAR at load time (gates commute); gates 1..KG-1 run
// as pure lane-splat FMA2 with zero swaps.
template<int KG>
__device__ __forceinline__ void do_group(float* __restrict__ sx,
                                         float* __restrict__ sy,
                                         const Group& grp, int tid) {
    const int NCOS = (DIM >> KG) / NTHREADS;   // 1 for KG=5, 2 for KG=4
    const int NU   = 1 << (KG - 1);            // packed slots per coset
    const float2* __restrict__ gm = &g_gates[grp.gbase][0];

    #pragma unroll
    for (int ci = 0; ci < NCOS; ci++) {
        unsigned c = (unsigned)tid + (unsigned)ci * NTHREADS;
        unsigned base = 0;
        #pragma unroll
        for (int b = 0; b < 14 - KG; b++)
            base |= ((c >> b) & 1u) << grp.npos[b];

        u64 XP[16], YP[16];

        // ---- gate 0 (scalar) fused with load + pack ----
        {
            bool sw = (__popc(base & (unsigned)grp.row[0]) & 1) != 0;
            float2 m0 = gm[0], m1 = gm[1], m2 = gm[2], m3 = gm[3];
            float v00x = sw ? m3.x : m0.x, v00y = sw ? m3.y : m0.y;
            float v01x = sw ? m2.x : m1.x, v01y = sw ? m2.y : m1.y;
            float v10x = sw ? m1.x : m2.x, v10y = sw ? m1.y : m2.y;
            float v11x = sw ? m0.x : m3.x, v11y = sw ? m0.y : m3.y;
            #pragma unroll
            for (int u = 0; u < NU; u++) {
                unsigned i0 = base ^ grp.loc2glob[2 * u];
                unsigned i1 = base ^ grp.loc2glob[2 * u + 1];
                float x0 = sx[i0], y0 = sy[i0];
                float x1 = sx[i1], y1 = sy[i1];
                float n0x = v00x * x0 - v00y * y0 + v01x * x1 - v01y * y1;
                float n0y = v00x * y0 + v00y * x0 + v01x * y1 + v01y * x1;
                float n1x = v10x * x0 - v10y * y0 + v11x * x1 - v11y * y1;
                float n1y = v10x * y0 + v10y * x0 + v11x * y1 + v11y * x1;
                PK2(XP[u], n0x, n1x);
                PK2(YP[u], n0y, n1y);
            }
        }

        // ---- gates 1..KG-1 (packed FMA2, lane-splat constants) ----
        #pragma unroll
        for (int j = 1; j < KG; j++) {
            bool sw = (__popc(base & (unsigned)grp.row[j]) & 1) != 0;
            float2 m0 = gm[j * 4 + 0], m1 = gm[j * 4 + 1];
            float2 m2 = gm[j * 4 + 2], m3 = gm[j * 4 + 3];
            float v00x = sw ? m3.x : m0.x, v00y = sw ? m3.y : m0.y;
            float v01x = sw ? m2.x : m1.x, v01y = sw ? m2.y : m1.y;
            float v10x = sw ? m1.x : m2.x, v10y = sw ? m1.y : m2.y;
            float v11x = sw ? m0.x : m3.x, v11y = sw ? m0.y : m3.y;
            u64 s00x, s00y, s00n, s01x, s01y, s01n;
            u64 s10x, s10y, s10n, s11x, s11y, s11n;
            PK2(s00x, v00x, v00x); PK2(s00y, v00y, v00y); PK2(s00n, -v00y, -v00y);
            PK2(s01x, v01x, v01x); PK2(s01y, v01y, v01y); PK2(s01n, -v01y, -v01y);
            PK2(s10x, v10x, v10x); PK2(s10y, v10y, v10y); PK2(s10n, -v10y, -v10y);
            PK2(s11x, v11x, v11x); PK2(s11y, v11y, v11y); PK2(s11n, -v11y, -v11y);

            const int bit = 1 << (j - 1);
            #pragma unroll
            for (int u = 0; u < NU; u++) {
                if (u & bit) continue;
                const int w = u | bit;
                u64 px = XP[u], py = YP[u], qx = XP[w], qy = YP[w];
                u64 t0, t1, t2, t3;
                MUL2(t0, s01n, qy); FMA2(t0, s01x, qx, t0);
                FMA2(t0, s00n, py, t0); FMA2(t0, s00x, px, t0);   // n0x
                MUL2(t1, s01y, qx); FMA2(t1, s01x, qy, t1);
                FMA2(t1, s00y, px, t1); FMA2(t1, s00x, py, t1);   // n0y
                MUL2(t2, s11n, qy); FMA2(t2, s11x, qx, t2);
                FMA2(t2, s10n, py, t2); FMA2(t2, s10x, px, t2);   // n1x
                MUL2(t3, s11y, qx); FMA2(t3, s11x, qy, t3);
                FMA2(t3, s10y, px, t3); FMA2(t3, s10x, py, t3);   // n1y
                XP[u] = t0; YP[u] = t1; XP[w] = t2; YP[w] = t3;
            }
        }

        // ---- unpack + store ----
        #pragma unroll
        for (int u = 0; u < NU; u++) {
            unsigned i0 = base ^ grp.loc2glob[2 * u];
            unsigned i1 = base ^ grp.loc2glob[2 * u + 1];
            float a0, a1, b0, b1;
            UPK2(a0, a1, XP[u]);
            UPK2(b0, b1, YP[u]);
            sx[i0] = a0; sx[i1] = a1;
            sy[i0] = b0; sy[i1] = b1;
        }
    }
}

__global__ __launch_bounds__(NTHREADS, 1)
void sim_kernel(const float* __restrict__ x, float* __restrict__ out, Tab2 tab) {
    extern __shared__ float sv[];          // [0,16384): x-plane, [16384,32768): y-plane
    float* sx = sv;
    float* sy = sv + DIM;
    __shared__ float ec[NQ], es[NQ];
    __shared__ float2 red[NWARPS];

    const int b   = blockIdx.x;
    const int tid = threadIdx.x;

    if (tid < NQ) {
        float h = x[b * NQ + tid] * 1.5707963267948966f;
        float svv, cv;
        sincosf(h, &svv, &cv);
        ec[tid] = cv;
        es[tid] = svv;
    }
    __syncthreads();

    // init: encoded real product state; qubit q at bit (13-q)
    float hi = 1.0f;
    #pragma unroll
    for (int q = 0; q < 9; q++)
        hi *= ((tid >> (8 - q)) & 1) ? es[q] : ec[q];
    #pragma unroll
    for (int l = 0; l < AMPS_PER_THREAD; l++) {
        float v = hi;
        #pragma unroll
        for (int q = 9; q < NQ; q++)
            v *= ((l >> (13 - q)) & 1) ? es[q] : ec[q];
        sx[tid * AMPS_PER_THREAD + l] = v;
        sy[tid * AMPS_PER_THREAD + l] = 0.0f;
    }
    __syncthreads();

    // 18 fused passes: per layer, groups of (5,5,4) commuting gates
    #pragma unroll 1
    for (int l = 0; l < NL; l++) {
        do_group<5>(sx, sy, tab.grp[l * 3 + 0], tid); __syncthreads();
        do_group<5>(sx, sy, tab.grp[l * 3 + 1], tid); __syncthreads();
        do_group<4>(sx, sy, tab.grp[l * 3 + 2], tid); __syncthreads();
    }

    // measurement: <Z_0>, <Z_1> via parity rows in stored coordinates
    float z0 = 0.0f, z1 = 0.0f;
    #pragma unroll
    for (int l = 0; l < AMPS_PER_THREAD; l++) {
        unsigned idx = (unsigned)(tid * AMPS_PER_THREAD + l);
        float xr = sx[idx], yi = sy[idx];
        float pr = xr * xr + yi * yi;
        z0 += (__popc(idx & tab.mrow0) & 1) ? -pr : pr;
        z1 += (__popc(idx & tab.mrow1) & 1) ? -pr : pr;
    }
    #pragma unroll
    for (int o = 16; o; o >>= 1) {
        z0 += __shfl_down_sync(0xffffffffu, z0, o);
        z1 += __shfl_down_sync(0xffffffffu, z1, o);
    }
    if ((tid & 31) == 0) red[tid >> 5] = make_float2(z0, z1);
    __syncthreads();
    if (tid == 0) {
        float a0 = 0.0f, a1 = 0.0f;
        #pragma unroll
        for (int w = 0; w < NWARPS; w++) { a0 += red[w].x; a1 += red[w].y; }
        out[b * 2 + 0] = a0;
        out[b * 2 + 1] = a1;
    }
}

extern "C" void kernel_launch(void* const* d_in, const int* in_sizes, int n_in,
                              void* d_out, int out_size) {
    const float* x = (const float*)d_in[0];       // (B, 14)
    const float* w = (const float*)d_in[1];       // (6, 14, 3)
    float* out = (float*)d_out;                   // (B, 2)
    const int B = in_sizes[0] / NQ;

    // --- host: GF(2) frame tracking + per-group echelon tables ---
    Tab2 tab;
    unsigned short R[NQ], Minv[NQ];
    for (int q = 0; q < NQ; q++)
        R[q] = Minv[q] = (unsigned short)(1u << (13 - q));

    for (int l = 0; l < NL; l++) {
        int offs[4] = {0, 5, 10, 14};             // groups of 5,5,4
        for (int gi = 0; gi < 3; gi++) {
            Group& G = tab.grp[l * 3 + gi];
            int off = offs[gi], kg = offs[gi + 1] - offs[gi];
            unsigned short m[5], r[5];
            for (int i = 0; i < kg; i++) {
                m[i] = Minv[off + i];
                r[i] = R[off + i];
                G.row[i] = r[i];
            }
            for (int i = kg; i < 5; i++) G.row[i] = 0;
            G.gbase = (unsigned char)(l * NQ + off);
            // echelonize to find pivot bits (highest-bit pivots)
            unsigned red_[5]; int piv[5];
            for (int i = 0; i < kg; i++) {
                unsigned v = m[i];
                for (int j = 0; j < i; j++)
                    if ((v >> piv[j]) & 1u) v ^= red_[j];
                int p = 31 - __builtin_clz(v);    // masks are linearly independent
                piv[i] = p; red_[i] = v;
            }
            bool ispiv[14] = {};
            for (int i = 0; i < kg; i++) ispiv[piv[i]] = true;
            int idx = 0;
            for (int bpos = 0; bpos < 14; bpos++)
                if (!ispiv[bpos]) G.npos[idx++] = (unsigned char)bpos;  // low bits -> lanes
            while (idx < 10) G.npos[idx++] = 0;
            // local->global XOR offsets from ORIGINAL masks (gate i <-> local bit i)
            for (int t = 0; t < 32; t++) {
                unsigned xr = 0;
                for (int i = 0; i < kg; i++)
                    if ((t >> i) & 1) xr ^= m[i];
                G.loc2glob[t] = (unsigned short)(t < (1 << kg) ? xr : 0);
            }
        }
        // layer's CNOT ring updates the frame (entering next layer)
        int r = (l % (NQ - 1)) + 1;
        for (int q = 0; q < NQ; q++) {
            int c = q, t = (q + r) % NQ;
            R[t]    ^= R[c];
            Minv[c] ^= Minv[t];
        }
    }
    tab.mrow0 = R[0];
    tab.mrow1 = R[1];

    cudaFuncSetAttribute(sim_kernel, cudaFuncAttributeMaxDynamicSharedMemorySize,
                         2 * DIM * (int)sizeof(float));

    prep_gates_kernel<<<1, 128>>>(w);
    sim_kernel<<<B, NTHREADS, 2 * DIM * sizeof(float)>>>(x, out, tab);
}